// round 1
// baseline (speedup 1.0000x reference)
#include <cuda_runtime.h>
#include <cuda_bf16.h>

// out[b, d] = x[b, d] * clamp(diagonal[d], -0.95, 0.95)
// BATCH = 16384, LATENT_DIM = 8192, fp32.
// Pure streaming kernel: 1 GiB total traffic, HBM-bound.

#define LATENT_DIM 8192
#define BATCH 16384
#define VEC 4                         // float4
#define COLS4 (LATENT_DIM / VEC)      // 2048 float4 per row
#define TPB 256                       // threads per block
#define BLOCKS_X (COLS4 / TPB)        // 8 blocks across a row

__global__ __launch_bounds__(TPB)
void diag_linear_kernel(const float4* __restrict__ x,
                        const float4* __restrict__ diag,
                        float4* __restrict__ out) {
    const int col4 = blockIdx.x * TPB + threadIdx.x;   // 0 .. 2047
    const long long row = blockIdx.y;                  // 0 .. 16383
    const long long idx = row * COLS4 + col4;

    // diagonal: 32 KiB, fully cache-resident after first wave
    float4 d = __ldg(&diag[col4]);
    d.x = fminf(fmaxf(d.x, -0.95f), 0.95f);
    d.y = fminf(fmaxf(d.y, -0.95f), 0.95f);
    d.z = fminf(fmaxf(d.z, -0.95f), 0.95f);
    d.w = fminf(fmaxf(d.w, -0.95f), 0.95f);

    float4 v = __ldg(&x[idx]);
    v.x *= d.x;
    v.y *= d.y;
    v.z *= d.z;
    v.w *= d.w;

    // Streaming store: output is never re-read by this kernel; avoid L2 pollution.
    __stcs(&out[idx], v);
}

extern "C" void kernel_launch(void* const* d_in, const int* in_sizes, int n_in,
                              void* d_out, int out_size) {
    const float4* x    = (const float4*)d_in[0];
    const float4* diag = (const float4*)d_in[1];
    float4* out        = (float4*)d_out;

    dim3 grid(BLOCKS_X, BATCH, 1);
    diag_linear_kernel<<<grid, TPB>>>(x, diag, out);
}

// round 2
// speedup vs baseline: 1.0024x; 1.0024x over previous
#include <cuda_runtime.h>
#include <cuda_bf16.h>

// out[b, d] = x[b, d] * clamp(diagonal[d], -0.95, 0.95)
// BATCH = 16384, LATENT_DIM = 8192, fp32. 1 GiB streamed, HBM-bound.
//
// R2: 4x LDG.128 per thread (MLP=4), __ldcs streaming reads on x,
//     __stcs streaming writes. Grid shrinks 4x; warp-coalesced unroll.

#define LATENT_DIM 8192
#define BATCH 16384
#define COLS4 (LATENT_DIM / 4)        // 2048 float4 per row
#define TPB 256
#define UNROLL 4
#define CHUNK (TPB * UNROLL)          // 1024 float4 per block
#define BLOCKS_X (COLS4 / CHUNK)      // 2 blocks across a row

__global__ __launch_bounds__(TPB)
void diag_linear_kernel(const float4* __restrict__ x,
                        const float4* __restrict__ diag,
                        float4* __restrict__ out) {
    const int base_col = blockIdx.x * CHUNK + threadIdx.x;   // warp-coalesced
    const long long row_off = (long long)blockIdx.y * COLS4;

    // Front-load 4 independent 16B loads (MLP=4). x is read-once: streaming hint.
    float4 v[UNROLL];
    float4 d[UNROLL];
#pragma unroll
    for (int k = 0; k < UNROLL; k++) {
        const int c = base_col + k * TPB;
        v[k] = __ldcs(&x[row_off + c]);
        d[k] = __ldg(&diag[c]);        // 32 KiB, stays hot in L1/L2
    }

#pragma unroll
    for (int k = 0; k < UNROLL; k++) {
        float4 s = d[k];
        s.x = fminf(fmaxf(s.x, -0.95f), 0.95f);
        s.y = fminf(fmaxf(s.y, -0.95f), 0.95f);
        s.z = fminf(fmaxf(s.z, -0.95f), 0.95f);
        s.w = fminf(fmaxf(s.w, -0.95f), 0.95f);
        v[k].x *= s.x;
        v[k].y *= s.y;
        v[k].z *= s.z;
        v[k].w *= s.w;
    }

#pragma unroll
    for (int k = 0; k < UNROLL; k++) {
        const int c = base_col + k * TPB;
        __stcs(&out[row_off + c], v[k]);   // evict-first streaming store
    }
}

extern "C" void kernel_launch(void* const* d_in, const int* in_sizes, int n_in,
                              void* d_out, int out_size) {
    const float4* x    = (const float4*)d_in[0];
    const float4* diag = (const float4*)d_in[1];
    float4* out        = (float4*)d_out;

    dim3 grid(BLOCKS_X, BATCH, 1);
    diag_linear_kernel<<<grid, TPB>>>(x, diag, out);
}